// round 15
// baseline (speedup 1.0000x reference)
#include <cuda_runtime.h>
#include <cuda_bf16.h>
#include <cuda_fp16.h>
#include <cstdint>
#include <math.h>

#define NB 2048
#define SL 64
#define NH 20
#define DEMB 300
#define HDIM 400
#define F1 200

// ---------------------------------------------------------------------------
// Global scratch
// ---------------------------------------------------------------------------
__device__ uint32_t g_Bh[1200 * 160];      // QKV weights, fp16 kpairs, XOR-swizzled
__device__ uint32_t g_W1h[25 * 200 * 8];   // W1 fp16 fragments
__device__ uint32_t g_ctxPhi[(size_t)1024 * 25 * 128 * 8]; // ctx fp16 fragments

__device__ __forceinline__ uint32_t pack_f16(float a, float b) {
    __half2 t = __floats2half2_rn(a, b);
    return *(uint32_t*)&t;
}
__device__ __forceinline__ uint32_t smem_u32(const void* p) {
    uint32_t a;
    asm("{ .reg .u64 t; cvta.to.shared.u64 t, %1; cvt.u32.u64 %0, t; }" : "=r"(a) : "l"(p));
    return a;
}
__device__ __forceinline__ float tanh_fast(float x) {
    float y;
    asm("tanh.approx.f32 %0, %1;" : "=f"(y) : "f"(x));
    return y;
}
__device__ __forceinline__ void mma16816h(float* d, const uint32_t* a, uint32_t b0, uint32_t b1) {
    asm volatile(
        "mma.sync.aligned.m16n8k16.row.col.f32.f16.f16.f32 "
        "{%0,%1,%2,%3}, {%4,%5,%6,%7}, {%8,%9}, {%0,%1,%2,%3};"
        : "+f"(d[0]), "+f"(d[1]), "+f"(d[2]), "+f"(d[3])
        : "r"(a[0]), "r"(a[1]), "r"(a[2]), "r"(a[3]), "r"(b0), "r"(b1));
}

#define MBARRIER_INIT(mbar, cnt) \
    asm volatile("mbarrier.init.shared.b64 [%0], %1;" :: "r"((uint32_t)(mbar)), "r"((uint32_t)(cnt)) : "memory")
#define MBARRIER_EXPECT_TX(mbar, tx) \
    asm volatile("mbarrier.arrive.expect_tx.shared.b64 _, [%0], %1;" :: "r"((uint32_t)(mbar)), "r"((uint32_t)(tx)) : "memory")
#define MBARRIER_ARRIVE(mbar) \
    asm volatile("mbarrier.arrive.shared.b64 _, [%0];" :: "r"((uint32_t)(mbar)) : "memory")
#define MBARRIER_WAIT_PARITY(mbar, par) do {                                     \
    uint32_t _m = (uint32_t)(mbar); uint32_t _p = (uint32_t)(par); uint32_t _d;  \
    asm volatile("{\n\t.reg .pred p;\n\t"                                        \
        "mbarrier.try_wait.parity.acquire.cta.shared::cta.b64 p, [%1], %2;\n\t"  \
        "selp.b32 %0, 1, 0, p;\n\t}" : "=r"(_d) : "r"(_m), "r"(_p) : "memory");  \
    if (!_d) {                                                                   \
        asm volatile("{\n\t.reg .pred P1;\n\t"                                   \
        "WAIT_LOOP_%=:\n\t"                                                      \
        "mbarrier.try_wait.parity.acquire.cta.shared::cta.b64 P1, [%0], %1, 0x989680;\n\t" \
        "@P1 bra.uni WAIT_DONE_%=;\n\t"                                          \
        "bra.uni WAIT_LOOP_%=;\n\t"                                              \
        "WAIT_DONE_%=:\n\t}" :: "r"(_m), "r"(_p) : "memory");                    \
    }                                                                            \
} while (0)
#define BULK_G2S(dst, src, bytes, bar)                                           \
    asm volatile("cp.async.bulk.shared::cluster.global.mbarrier::complete_tx::bytes [%0], [%1], %2, [%3];" \
        :: "r"((uint32_t)(dst)), "l"(src), "r"((uint32_t)(bytes)), "r"((uint32_t)(bar)) : "memory")

// ---------------------------------------------------------------------------
// Kernel 1: weight conversion (unchanged)
// ---------------------------------------------------------------------------
__global__ void convert_w(const float* __restrict__ WQ,
                          const float* __restrict__ WK,
                          const float* __restrict__ WV,
                          const float* __restrict__ W1)
{
    int idx = blockIdx.x * 256 + threadIdx.x;
    if (idx < 1200 * 160) {
        int n = idx / 160, p = idx % 160;
        int mat = n / 400, col = n - mat * 400;
        const float* W = (mat == 0) ? WQ : (mat == 1) ? WK : WV;
        int k = 2 * p;
        float w0 = (k < DEMB) ? W[k * 400 + col] : 0.f;
        float w1 = (k + 1 < DEMB) ? W[(k + 1) * 400 + col] : 0.f;
        int dst = n * 160 + (p ^ (4 * (n & 7)));
        g_Bh[dst] = pack_f16(w0, w1);
    } else if (idx < 1200 * 160 + 200 * 200) {
        int j = idx - 1200 * 160;
        int col = j % 200, p = j / 200;
        float w0 = W1[(2 * p) * 200 + col];
        float w1 = W1[(2 * p + 1) * 200 + col];
        int dst = (p >> 3) * 1600 + col * 8 + ((p & 7) ^ (4 * ((col >> 2) & 1)));
        g_W1h[dst] = pack_f16(w0, w1);
    }
}

// ---------------------------------------------------------------------------
// Kernel 2: FUSED gemm + per-head-pair attention + pooling
//   chunk order: (Q,K,V) per head-pair; QKV fragments never leave smem
// ---------------------------------------------------------------------------
#define XW 164
#define GW_BUF0 0
#define GW_BUF1 6400
#define GW_SOUT 12800      // single sout [40][132] = 5280 words
#define QW_Q    18080      // [hl][tok 128][12] = 3072 words
#define QW_K    21152      // 3072
#define QW_V    24224      // [row][hl][j 24][36] = 3456
#define GW_XHI  0          // x gather overlay (phase A only)
#define GW_MBAR 27680      // gemm bars (2 x 8B)
#define P3_FULL 27684      // pool full bars (3 x 8B)
#define P3_EMPT 27690      // pool empty bars (3 x 8B)
// phase-3 pool overlays low words
#define P3_SLOT 1856
#define P3_B1   5568
#define P3_W2   5768
#define P3_LP   5968
#define P3_LOG  6096
#define P3_SUM  6224
#define SMEM_GA (27696 * 4)

__global__ __launch_bounds__(256, 2)
void gemm_attn(const int*   __restrict__ text,
               const float* __restrict__ emb,
               const float* __restrict__ bQ,
               const float* __restrict__ bK,
               const float* __restrict__ bV,
               const float* __restrict__ b1,
               const float* __restrict__ W2,
               const float* __restrict__ b2,
               float* __restrict__ out)
{
    extern __shared__ uint32_t sg[];
    const uint32_t sbase = smem_u32(sg);
    const int tid = threadIdx.x;
    const int lane = tid & 31;
    const int wid = tid >> 5;
    const int q = lane & 3;
    const int g = lane >> 2;
    const int bp = blockIdx.x;
    const uint32_t bar0 = sbase + GW_MBAR * 4;
    const uint32_t bar1 = bar0 + 8;
    const uint32_t pFull  = sbase + P3_FULL * 4;
    const uint32_t pEmpty = sbase + P3_EMPT * 4;

    if (tid == 0) {
        MBARRIER_INIT(bar0, 1); MBARRIER_INIT(bar1, 1);
        #pragma unroll
        for (int i = 0; i < 3; i++) {
            MBARRIER_INIT(pFull + i * 8, 1);
            MBARRIER_INIT(pEmpty + i * 8, 8);
        }
    }

    // ================= Phase A: x gather -> A fragments =================
    uint32_t* xhi = sg + GW_XHI;
    for (int i = tid; i < 128 * 14; i += 256) {
        int r = i / 14, w = 150 + i % 14;
        xhi[r * XW + w] = 0;
    }
    {
        const float4* emb4 = (const float4*)emb;
        const int* trow = text + bp * 128;
        for (int i = tid; i < 128 * 75; i += 256) {
            int r = i / 75, c = i % 75;
            int tok = trow[r];
            float4 v = emb4[(size_t)tok * 75 + c];
            xhi[r * XW + 2 * c]     = pack_f16(v.x, v.y);
            xhi[r * XW + 2 * c + 1] = pack_f16(v.z, v.w);
        }
    }
    __syncthreads();

    uint32_t ahi[20][4];
    {
        const int r0 = wid * 16 + g;
        const int r1 = r0 + 8;
        #pragma unroll
        for (int kk = 0; kk < 20; kk++) {
            int w0 = 8 * kk + q;
            ahi[kk][0] = xhi[r0 * XW + w0];
            ahi[kk][1] = xhi[r1 * XW + w0];
            ahi[kk][2] = xhi[r0 * XW + w0 + 4];
            ahi[kk][3] = xhi[r1 * XW + w0 + 4];
        }
    }
    __syncthreads();   // x region dead

    auto prefetch = [&](int s) {       // step s: chunk = (s%3)*10 + s/3
        int c = (s % 3) * 10 + s / 3;
        uint32_t bar = (s & 1) ? bar1 : bar0;
        MBARRIER_EXPECT_TX(bar, 25600);
        BULK_G2S(sbase + ((s & 1) ? GW_BUF1 : GW_BUF0) * 4, g_Bh + c * 6400, 25600, bar);
    };
    if (tid == 0) prefetch(0);

    const int key = g << 2;
    const int strip = wid * 16;
    const int tok0 = strip + g;
    const int rowoff = (wid >> 2) * 64;
    const size_t pb25 = (size_t)bp * 25;
    float* sout = (float*)(sg + GW_SOUT);

    for (int s = 0; s < 30; s++) {
        const int mat = s % 3, hp = s / 3;
        if (s + 1 < 30 && tid == 0) prefetch(s + 1);
        MBARRIER_WAIT_PARITY((s & 1) ? bar1 : bar0, (s >> 1) & 1);

        const uint32_t* Bh = sg + ((s & 1) ? GW_BUF1 : GW_BUF0);
        const int r0 = wid * 16 + g;

        #pragma unroll
        for (int i = 0; i < 5; i++) {
            float acc0[4] = {0.f, 0.f, 0.f, 0.f};
            float acc1[4] = {0.f, 0.f, 0.f, 0.f};
            const int base = (i * 8 + g) * 160;
            #pragma unroll
            for (int kk = 0; kk < 20; kk += 2) {
                int w0 = (8 * kk + q) ^ key;
                int w1 = (8 * (kk + 1) + q) ^ key;
                mma16816h(acc0, ahi[kk],     Bh[base + w0], Bh[base + (w0 ^ 4)]);
                mma16816h(acc1, ahi[kk + 1], Bh[base + w1], Bh[base + (w1 ^ 4)]);
            }
            int cl = i * 8 + 2 * q;
            sout[cl * 132 + r0]           = acc0[0] + acc1[0];
            sout[(cl + 1) * 132 + r0]     = acc0[1] + acc1[1];
            sout[cl * 132 + r0 + 8]       = acc0[2] + acc1[2];
            sout[(cl + 1) * 132 + r0 + 8] = acc0[3] + acc1[3];
        }
        __syncthreads();

        // ---- epilogue: sout -> QKV fragments in SMEM ----
        const float* bias = (mat == 0) ? bQ : (mat == 1) ? bK : bV;
        if (mat < 2) {
            const int hl = tid >> 7, tok = tid & 127;
            uint32_t* dh = sg + ((mat == 0) ? QW_Q : QW_K) + (hl * 128 + tok) * 12;
            uint32_t hw[12];
            #pragma unroll
            for (int p = 0; p < 10; p++) {
                int cl = hl * 20 + 2 * p;
                float v0 = sout[cl * 132 + tok]       + __ldg(bias + hp * 40 + cl);
                float v1 = sout[(cl + 1) * 132 + tok] + __ldg(bias + hp * 40 + cl + 1);
                hw[p] = pack_f16(v0, v1);
            }
            hw[10] = hw[11] = 0;
            #pragma unroll
            for (int u = 0; u < 3; u++)
                ((uint4*)dh)[u] = make_uint4(hw[4*u], hw[4*u+1], hw[4*u+2], hw[4*u+3]);
        } else if (tid < 160) {
            const int hl = tid / 80, r = tid % 80, j = r >> 2, qt = r & 3;
            const int row = qt >> 1;
            const float bb = __ldg(bias + hp * 40 + hl * 20 + j);
            uint32_t hv[16];
            #pragma unroll
            for (int i = 0; i < 16; i++) {
                int t = qt * 32 + 2 * i;
                float v0 = sout[(hl * 20 + j) * 132 + t]     + bb;
                float v1 = sout[(hl * 20 + j) * 132 + t + 1] + bb;
                hv[i] = pack_f16(v0, v1);
            }
            uint32_t* dh = sg + QW_V + row * 1728 + hl * 864 + j * 36 + 16 * (qt & 1);
            #pragma unroll
            for (int u = 0; u < 4; u++)
                ((uint4*)dh)[u] = make_uint4(hv[4*u], hv[4*u+1], hv[4*u+2], hv[4*u+3]);
        }
        __syncthreads();

        // ---- after (Q,K,V) triple: attention for heads 2hp, 2hp+1 ----
        if (mat == 2) {
            #pragma unroll 1
            for (int hl = 0; hl < 2; hl++) {
                const uint32_t* Qh = sg + QW_Q + hl * 1536;
                const uint32_t* Kh = sg + QW_K + hl * 1536;
                const uint32_t* Vh = sg + QW_V + (wid >> 2) * 1728 + hl * 864;

                const int ra = tok0 * 12, rb2 = (tok0 + 8) * 12;
                uint32_t qh0[4] = { Qh[ra + q], Qh[rb2 + q], Qh[ra + q + 4], Qh[rb2 + q + 4] };
                uint32_t qh1[4] = { Qh[ra + 8 + q], Qh[rb2 + 8 + q], 0, 0 };

                float rs0 = 0.f, rs8 = 0.f;
                uint32_t ph[4][4];
                #pragma unroll
                for (int nt = 0; nt < 8; nt++) {
                    float e4[4] = {0.f, 0.f, 0.f, 0.f};
                    const int n = (rowoff + 8 * nt + g) * 12;
                    mma16816h(e4, qh0, Kh[n + q], Kh[n + q + 4]);
                    mma16816h(e4, qh1, Kh[n + 8 + q], 0u);
                    float e0 = __expf(e4[0] * 0.22360679774997896f);
                    float e1 = __expf(e4[1] * 0.22360679774997896f);
                    float e2 = __expf(e4[2] * 0.22360679774997896f);
                    float e3 = __expf(e4[3] * 0.22360679774997896f);
                    rs0 += e0 + e1; rs8 += e2 + e3;
                    ph[nt >> 1][2 * (nt & 1) + 0] = pack_f16(e0, e1);
                    ph[nt >> 1][2 * (nt & 1) + 1] = pack_f16(e2, e3);
                }
                rs0 += __shfl_xor_sync(0xffffffffu, rs0, 1);
                rs0 += __shfl_xor_sync(0xffffffffu, rs0, 2);
                rs8 += __shfl_xor_sync(0xffffffffu, rs8, 1);
                rs8 += __shfl_xor_sync(0xffffffffu, rs8, 2);

                float cxa[12], cxb[12];
                #pragma unroll
                for (int i = 0; i < 12; i++) { cxa[i] = 0.f; cxb[i] = 0.f; }
                #pragma unroll
                for (int t = 0; t < 4; t += 2) {
                    #pragma unroll
                    for (int nj = 0; nj < 3; nj++) {
                        const int na = (8 * nj + g) * 36 + 8 * t;
                        const int nb = na + 8;
                        mma16816h(cxa + nj * 4, ph[t],     Vh[na + q], Vh[na + q + 4]);
                        mma16816h(cxb + nj * 4, ph[t + 1], Vh[nb + q], Vh[nb + q + 4]);
                    }
                }

                const float i0 = 1.f / (rs0 + 1e-8f);
                const float i8 = 1.f / (rs8 + 1e-8f);
                const int h = 2 * hp + hl;
                #pragma unroll
                for (int nj = 0; nj < 3; nj++) {
                    const int j0 = 8 * nj + 2 * q;
                    if (j0 < 20) {
                        float a0 = (cxa[nj*4+0] + cxb[nj*4+0]) * i0;
                        float a1 = (cxa[nj*4+1] + cxb[nj*4+1]) * i0;
                        float a2 = (cxa[nj*4+2] + cxb[nj*4+2]) * i8;
                        float a3 = (cxa[nj*4+3] + cxb[nj*4+3]) * i8;
                        const int p = 10 * h + 4 * nj + q;
                        const int pl7 = (p & 7) ^ (4 * ((tok0 >> 2) & 1));
                        const size_t base = (pb25 + (p >> 3)) * 128;
                        g_ctxPhi[(base + tok0) * 8 + pl7]     = pack_f16(a0, a1);
                        g_ctxPhi[(base + tok0 + 8) * 8 + pl7] = pack_f16(a2, a3);
                    }
                }
            }
            __syncthreads();   // QKV smem free for next head-pair
        }
    }

    __threadfence();
    __syncthreads();

    // ================= Phase 3: pooling (own 2 batch rows) =================
    float* b1s = (float*)(sg + P3_B1);
    float* w2s = (float*)(sg + P3_W2);
    float* lp  = (float*)(sg + P3_LP);
    if (tid < 200) { b1s[tid] = b1[tid]; w2s[tid] = W2[tid]; }
    __syncthreads();

    const int c8 = lane >> 2;
    const int pkey = c8 & 4;
    const int q0 = q ^ pkey, q1 = q0 ^ 4;
    const int pr0 = wid * 16 + c8;

    auto pstage = [&](int ks) {                        // ks in [0,50)
        MBARRIER_WAIT_PARITY(pEmpty + (ks % 3) * 8, 1 ^ ((ks / 3) & 1));
        uint32_t bar = pFull + (ks % 3) * 8;
        int pass = ks / 25, k = ks % 25;
        uint32_t wbytes = pass ? 3072u : 3328u;
        MBARRIER_EXPECT_TX(bar, 4096 + wbytes);
        uint32_t d = sbase + (ks % 3) * P3_SLOT * 4;
        BULK_G2S(d,        g_ctxPhi + (pb25 + k) * 1024, 4096, bar);
        BULK_G2S(d + 4096, g_W1h + k * 1600 + pass * 832, wbytes, bar);
    };
    if (tid == 0) { pstage(0); pstage(1); pstage(2); }

    for (int pass = 0; pass < 2; pass++) {
        const int ntile = pass ? 12 : 13;
        const int tbase = pass * 13;
        float acc[52];
        #pragma unroll
        for (int i = 0; i < 52; i++) acc[i] = 0.f;

        for (int k = 0; k < 25; k++) {
            const int ks = pass * 25 + k;
            MBARRIER_WAIT_PARITY(pFull + (ks % 3) * 8, (ks / 3) & 1);

            const uint32_t* A  = sg + (ks % 3) * P3_SLOT;
            const uint32_t* Bh = A + 1024;

            uint32_t fh[4];
            fh[0] = A[pr0 * 8 + q0]; fh[1] = A[(pr0 + 8) * 8 + q0];
            fh[2] = A[pr0 * 8 + q1]; fh[3] = A[(pr0 + 8) * 8 + q1];

            #pragma unroll
            for (int t = 0; t < 13; t++) {
                if (t < ntile) {
                    const int cb = (t * 8 + c8) * 8;
                    mma16816h(acc + t * 4, fh, Bh[cb + q0], Bh[cb + q1]);
                }
            }
            if (lane == 0) MBARRIER_ARRIVE(pEmpty + (ks % 3) * 8);
            if (ks + 3 < 50 && tid == 0) pstage(ks + 3);
        }

        float part0 = 0.f, part8 = 0.f;
        #pragma unroll
        for (int t = 0; t < 13; t++) {
            if (t < ntile) {
                int c0 = (tbase + t) * 8 + 2 * q;
                part0 += tanh_fast(acc[t * 4 + 0] + b1s[c0])     * w2s[c0];
                part0 += tanh_fast(acc[t * 4 + 1] + b1s[c0 + 1]) * w2s[c0 + 1];
                part8 += tanh_fast(acc[t * 4 + 2] + b1s[c0])     * w2s[c0];
                part8 += tanh_fast(acc[t * 4 + 3] + b1s[c0 + 1]) * w2s[c0 + 1];
            }
        }
        part0 += __shfl_xor_sync(0xffffffffu, part0, 1);
        part0 += __shfl_xor_sync(0xffffffffu, part0, 2);
        part8 += __shfl_xor_sync(0xffffffffu, part8, 1);
        part8 += __shfl_xor_sync(0xffffffffu, part8, 2);
        if (q == 0) {
            if (pass == 0) { lp[pr0] = part0; lp[pr0 + 8] = part8; }
            else           { lp[pr0] += part0; lp[pr0 + 8] += part8; }
        }
    }
    __syncthreads();

    float* logit = (float*)(sg + P3_LOG);
    float* ssum  = (float*)(sg + P3_SUM);
    const float b2v = b2[0];
    if (tid < 128) logit[tid] = __expf(lp[tid] + b2v);
    __syncthreads();
    if (wid < 2) {
        float v = logit[wid * 64 + lane] + logit[wid * 64 + lane + 32];
        #pragma unroll
        for (int off = 16; off; off >>= 1) v += __shfl_xor_sync(0xffffffffu, v, off);
        if (lane == 0) ssum[wid] = v;
    }
    __syncthreads();

    if (tid < 200) {
        const int p = tid;
        const size_t fbase = (pb25 + (p >> 3)) * 128;
        const int ple = p & 7;
        #pragma unroll
        for (int bh = 0; bh < 2; bh++) {
            const float inv = 1.f / (ssum[bh] + 1e-8f);
            const float* lg = logit + bh * 64;
            float ax = 0.f, ay = 0.f;
            #pragma unroll 4
            for (int l = 0; l < 64; l++) {
                const int t = bh * 64 + l;
                uint32_t w32 = g_ctxPhi[(fbase + t) * 8 + (ple ^ (4 * ((t >> 2) & 1)))];
                __half2 hv = *(__half2*)&w32;
                float w = lg[l];
                ax += w * __low2float(hv);
                ay += w * __high2float(hv);
            }
            ((float2*)out)[(size_t)(bp * 2 + bh) * 200 + p] = make_float2(ax * inv, ay * inv);
        }
    }
}

// ---------------------------------------------------------------------------
extern "C" void kernel_launch(void* const* d_in, const int* in_sizes, int n_in,
                              void* d_out, int out_size) {
    const int*   text = (const int*)  d_in[0];
    const float* emb  = (const float*)d_in[1];
    const float* WQ   = (const float*)d_in[2];
    const float* bQ   = (const float*)d_in[3];
    const float* WK   = (const float*)d_in[4];
    const float* bK   = (const float*)d_in[5];
    const float* WV   = (const float*)d_in[6];
    const float* bV   = (const float*)d_in[7];
    const float* W1   = (const float*)d_in[8];
    const float* b1   = (const float*)d_in[9];
    const float* W2   = (const float*)d_in[10];
    const float* b2   = (const float*)d_in[11];
    float* out = (float*)d_out;

    convert_w<<<(1200 * 160 + 200 * 200 + 255) / 256, 256>>>(WQ, WK, WV, W1);

    cudaFuncSetAttribute(gemm_attn, cudaFuncAttributeMaxDynamicSharedMemorySize, SMEM_GA);
    gemm_attn<<<NB / 2, 256, SMEM_GA>>>(text, emb, bQ, bK, bV, b1, W2, b2, out);
}

// round 16
// speedup vs baseline: 1.3618x; 1.3618x over previous
#include <cuda_runtime.h>
#include <cuda_bf16.h>
#include <cuda_fp16.h>
#include <cstdint>
#include <math.h>

#define NB 2048
#define SL 64
#define NH 20
#define DEMB 300
#define HDIM 400
#define F1 200

// ---------------------------------------------------------------------------
// Global scratch (all operand tensors single fp16)
// ---------------------------------------------------------------------------
__device__ uint32_t g_Bh[1200 * 160];      // QKV weights, fp16 kpairs, LDS64-paired layout
__device__ uint32_t g_W1h[25 * 200 * 8];   // W1 fp16 fragments
__device__ uint32_t g_Qhi[(size_t)1024 * 20 * 128 * 12];  // Q fp16 [pair][head][tok][12]
__device__ uint32_t g_Khi[(size_t)1024 * 20 * 128 * 12];  // K fp16
__device__ uint32_t g_Vhi[(size_t)2048 * 20 * 24 * 36];   // V fp16 [row][head][j][36]
__device__ uint32_t g_ctxPhi[(size_t)1024 * 25 * 128 * 8]; // ctx fp16 fragments

__device__ __forceinline__ uint32_t pack_f16(float a, float b) {
    __half2 t = __floats2half2_rn(a, b);
    return *(uint32_t*)&t;
}
__device__ __forceinline__ uint32_t smem_u32(const void* p) {
    uint32_t a;
    asm("{ .reg .u64 t; cvta.to.shared.u64 t, %1; cvt.u32.u64 %0, t; }" : "=r"(a) : "l"(p));
    return a;
}
__device__ __forceinline__ float tanh_fast(float x) {
    float y;
    asm("tanh.approx.f32 %0, %1;" : "=f"(y) : "f"(x));
    return y;
}
__device__ __forceinline__ void mma16816h(float* d, const uint32_t* a, uint32_t b0, uint32_t b1) {
    asm volatile(
        "mma.sync.aligned.m16n8k16.row.col.f32.f16.f16.f32 "
        "{%0,%1,%2,%3}, {%4,%5,%6,%7}, {%8,%9}, {%0,%1,%2,%3};"
        : "+f"(d[0]), "+f"(d[1]), "+f"(d[2]), "+f"(d[3])
        : "r"(a[0]), "r"(a[1]), "r"(a[2]), "r"(a[3]), "r"(b0), "r"(b1));
}

#define MBARRIER_INIT(mbar, cnt) \
    asm volatile("mbarrier.init.shared.b64 [%0], %1;" :: "r"((uint32_t)(mbar)), "r"((uint32_t)(cnt)) : "memory")
#define MBARRIER_EXPECT_TX(mbar, tx) \
    asm volatile("mbarrier.arrive.expect_tx.shared.b64 _, [%0], %1;" :: "r"((uint32_t)(mbar)), "r"((uint32_t)(tx)) : "memory")
#define MBARRIER_ARRIVE(mbar) \
    asm volatile("mbarrier.arrive.shared.b64 _, [%0];" :: "r"((uint32_t)(mbar)) : "memory")
#define MBARRIER_WAIT_PARITY(mbar, par) do {                                     \
    uint32_t _m = (uint32_t)(mbar); uint32_t _p = (uint32_t)(par); uint32_t _d;  \
    asm volatile("{\n\t.reg .pred p;\n\t"                                        \
        "mbarrier.try_wait.parity.acquire.cta.shared::cta.b64 p, [%1], %2;\n\t"  \
        "selp.b32 %0, 1, 0, p;\n\t}" : "=r"(_d) : "r"(_m), "r"(_p) : "memory");  \
    if (!_d) {                                                                   \
        asm volatile("{\n\t.reg .pred P1;\n\t"                                   \
        "WAIT_LOOP_%=:\n\t"                                                      \
        "mbarrier.try_wait.parity.acquire.cta.shared::cta.b64 P1, [%0], %1, 0x989680;\n\t" \
        "@P1 bra.uni WAIT_DONE_%=;\n\t"                                          \
        "bra.uni WAIT_LOOP_%=;\n\t"                                              \
        "WAIT_DONE_%=:\n\t}" :: "r"(_m), "r"(_p) : "memory");                    \
    }                                                                            \
} while (0)
#define BULK_G2S(dst, src, bytes, bar)                                           \
    asm volatile("cp.async.bulk.shared::cluster.global.mbarrier::complete_tx::bytes [%0], [%1], %2, [%3];" \
        :: "r"((uint32_t)(dst)), "l"(src), "r"((uint32_t)(bytes)), "r"((uint32_t)(bar)) : "memory")

// ---------------------------------------------------------------------------
// Kernel 1: weight conversion (B fragments in LDS64-paired layout)
// ---------------------------------------------------------------------------
__global__ void convert_w(const float* __restrict__ WQ,
                          const float* __restrict__ WK,
                          const float* __restrict__ WV,
                          const float* __restrict__ W1)
{
    int idx = blockIdx.x * 256 + threadIdx.x;
    if (idx < 1200 * 160) {
        int n = idx / 160, p = idx % 160;
        int mat = n / 400, col = n - mat * 400;
        const float* W = (mat == 0) ? WQ : (mat == 1) ? WK : WV;
        int k = 2 * p;
        float w0 = (k < DEMB) ? W[k * 400 + col] : 0.f;
        float w1 = (k + 1 < DEMB) ? W[(k + 1) * 400 + col] : 0.f;
        // pair the two mma b-operand words adjacently: newp = 8kk + 2q + half
        int newp = (p & ~7) | (2 * (p & 3)) | ((p >> 2) & 1);
        int gg = n & 7;
        int sw = ((gg & 3) << 3) | (((gg >> 2) & 1) << 1);
        g_Bh[n * 160 + (newp ^ sw)] = pack_f16(w0, w1);
    } else if (idx < 1200 * 160 + 200 * 200) {
        int j = idx - 1200 * 160;
        int col = j % 200, p = j / 200;
        float w0 = W1[(2 * p) * 200 + col];
        float w1 = W1[(2 * p + 1) * 200 + col];
        int dst = (p >> 3) * 1600 + col * 8 + ((p & 7) ^ (4 * ((col >> 2) & 1)));
        g_W1h[dst] = pack_f16(w0, w1);
    }
}

// ---------------------------------------------------------------------------
// Kernel 2: FUSED QKV GEMM + attention + pooling (R14 structure)
// ---------------------------------------------------------------------------
#define XW 164
#define GW_BUF0 0
#define GW_BUF1 6400
#define GW_SOUT0 12800
#define GW_SOUT1 18080
#define GW_XHI  0
#define GW_BIAS 23360
#define GW_MBAR 24560      // gemm bars (2)
#define AT_BUF  4800       // attn buffers overlay words [0, 14400)
#define AT_FULL 24564      // attn full bars (3)
#define AT_EMPT 24570      // attn empty bars (3)
// phase-3 (pool) layout (overlays low words)
#define P3_SLOT 1856
#define P3_B1   5568
#define P3_W2   5768
#define P3_LP   5968
#define P3_LOG  6096
#define P3_SUM  6224
#define P3_FULL 24576
#define P3_EMPT 24582
#define SMEM_GA (24592 * 4)

__global__ __launch_bounds__(256, 2)
void gemm_attn(const int*   __restrict__ text,
               const float* __restrict__ emb,
               const float* __restrict__ bQ,
               const float* __restrict__ bK,
               const float* __restrict__ bV,
               const float* __restrict__ b1,
               const float* __restrict__ W2,
               const float* __restrict__ b2,
               float* __restrict__ out)
{
    extern __shared__ uint32_t sg[];
    const uint32_t sbase = smem_u32(sg);
    const int tid = threadIdx.x;
    const int lane = tid & 31;
    const int wid = tid >> 5;
    const int q = lane & 3;
    const int g = lane >> 2;
    const int bp = blockIdx.x;
    const uint32_t bar0 = sbase + GW_MBAR * 4;
    const uint32_t bar1 = bar0 + 8;
    const uint32_t fullB  = sbase + AT_FULL * 4;
    const uint32_t emptyB = sbase + AT_EMPT * 4;
    const uint32_t pFull  = sbase + P3_FULL * 4;
    const uint32_t pEmpty = sbase + P3_EMPT * 4;

    if (tid == 0) {
        MBARRIER_INIT(bar0, 1); MBARRIER_INIT(bar1, 1);
        #pragma unroll
        for (int i = 0; i < 3; i++) {
            MBARRIER_INIT(fullB + i * 8, 1);
            MBARRIER_INIT(emptyB + i * 8, 8);
            MBARRIER_INIT(pFull + i * 8, 1);
            MBARRIER_INIT(pEmpty + i * 8, 8);
        }
    }

    float* bias_s = (float*)(sg + GW_BIAS);
    for (int i = tid; i < 400; i += 256) {
        bias_s[i] = bQ[i]; bias_s[400 + i] = bK[i]; bias_s[800 + i] = bV[i];
    }

    // ================= Phase 1: QKV GEMM =================
    uint32_t* xhi = sg + GW_XHI;
    for (int i = tid; i < 128 * 14; i += 256) {
        int r = i / 14, w = 150 + i % 14;
        xhi[r * XW + w] = 0;
    }
    {
        const float4* emb4 = (const float4*)emb;
        const int* trow = text + bp * 128;
        for (int i = tid; i < 128 * 75; i += 256) {
            int r = i / 75, c = i % 75;
            int tok = trow[r];
            float4 v = emb4[(size_t)tok * 75 + c];
            xhi[r * XW + 2 * c]     = pack_f16(v.x, v.y);
            xhi[r * XW + 2 * c + 1] = pack_f16(v.z, v.w);
        }
    }
    __syncthreads();

    uint32_t ahi[20][4];
    {
        const int r0 = wid * 16 + g;
        const int r1 = r0 + 8;
        #pragma unroll
        for (int kk = 0; kk < 20; kk++) {
            int w0 = 8 * kk + q;
            ahi[kk][0] = xhi[r0 * XW + w0];
            ahi[kk][1] = xhi[r1 * XW + w0];
            ahi[kk][2] = xhi[r0 * XW + w0 + 4];
            ahi[kk][3] = xhi[r1 * XW + w0 + 4];
        }
    }
    __syncthreads();   // x region dead

    auto prefetch = [&](int chunk, uint32_t dstw, uint32_t bar) {
        MBARRIER_EXPECT_TX(bar, 25600);
        BULK_G2S(sbase + dstw * 4, g_Bh + chunk * 6400, 25600, bar);
    };
    if (tid == 0) prefetch(0, GW_BUF0, bar0);

    const int sw = ((g & 3) << 3) | (((g >> 2) & 1) << 1);

    for (int c = 0; c < 30; c++) {
        if (c + 1 < 30 && tid == 0)
            prefetch(c + 1, (c & 1) ? GW_BUF0 : GW_BUF1, (c & 1) ? bar0 : bar1);
        MBARRIER_WAIT_PARITY((c & 1) ? bar1 : bar0, (c >> 1) & 1);

        const uint32_t* Bh = sg + ((c & 1) ? GW_BUF1 : GW_BUF0);
        float* sout = (float*)(sg + ((c & 1) ? GW_SOUT1 : GW_SOUT0));
        const int r0 = wid * 16 + g;

        #pragma unroll
        for (int i = 0; i < 5; i++) {
            float acc0[4] = {0.f, 0.f, 0.f, 0.f};
            float acc1[4] = {0.f, 0.f, 0.f, 0.f};
            const int base = (i * 8 + g) * 160;
            #pragma unroll
            for (int kk = 0; kk < 20; kk += 2) {
                uint2 b0 = *(const uint2*)(Bh + base + ((8 * kk + 2 * q) ^ sw));
                uint2 b1 = *(const uint2*)(Bh + base + ((8 * (kk + 1) + 2 * q) ^ sw));
                mma16816h(acc0, ahi[kk],     b0.x, b0.y);
                mma16816h(acc1, ahi[kk + 1], b1.x, b1.y);
            }
            int cl = i * 8 + 2 * q;
            sout[cl * 132 + r0]           = acc0[0] + acc1[0];
            sout[(cl + 1) * 132 + r0]     = acc0[1] + acc1[1];
            sout[cl * 132 + r0 + 8]       = acc0[2] + acc1[2];
            sout[(cl + 1) * 132 + r0 + 8] = acc0[3] + acc1[3];
        }
        __syncthreads();

        const int mat = c / 10, hpair = c % 10;
        if (mat < 2) {
            const int hl = tid >> 7, tok = tid & 127;
            const int head = hpair * 2 + hl;
            size_t rb = (((size_t)bp * 20 + head) * 128 + tok) * 12;
            uint32_t hw[12];
            #pragma unroll
            for (int p = 0; p < 10; p++) {
                int cl = hl * 20 + 2 * p;
                float v0 = sout[cl * 132 + tok]       + bias_s[c * 40 + cl];
                float v1 = sout[(cl + 1) * 132 + tok] + bias_s[c * 40 + cl + 1];
                hw[p] = pack_f16(v0, v1);
            }
            hw[10] = hw[11] = 0;
            uint32_t* dh = (mat ? g_Khi : g_Qhi) + rb;
            #pragma unroll
            for (int u = 0; u < 3; u++)
                ((uint4*)dh)[u] = make_uint4(hw[4*u], hw[4*u+1], hw[4*u+2], hw[4*u+3]);
        } else if (tid < 160) {
            const int hl = tid / 80, r = tid % 80, j = r >> 2, qt = r & 3;
            const int head = hpair * 2 + hl, row = qt >> 1;
            const float bb = bias_s[c * 40 + hl * 20 + j];
            uint32_t hv[16];
            #pragma unroll
            for (int i = 0; i < 16; i++) {
                int t = qt * 32 + 2 * i;
                float v0 = sout[(hl * 20 + j) * 132 + t]     + bb;
                float v1 = sout[(hl * 20 + j) * 132 + t + 1] + bb;
                hv[i] = pack_f16(v0, v1);
            }
            size_t vb = (((size_t)(bp * 2 + row) * 20 + head) * 24 + j) * 36 + 16 * (qt & 1);
            uint32_t* dh = g_Vhi + vb;
            #pragma unroll
            for (int u = 0; u < 4; u++)
                ((uint4*)dh)[u] = make_uint4(hv[4*u], hv[4*u+1], hv[4*u+2], hv[4*u+3]);
        }
    }

    __threadfence();
    __syncthreads();

    // ================= Phase 2: attention =================
    const int strip = wid * 16;
    const int rowoff = (wid >> 2) * 64;

    auto stage = [&](int h) {
        MBARRIER_WAIT_PARITY(emptyB + (h % 3) * 8, 1 ^ ((h / 3) & 1));
        uint32_t bar = fullB + (h % 3) * 8;
        uint32_t d = sbase + (h % 3) * AT_BUF * 4;
        MBARRIER_EXPECT_TX(bar, 19200);
        size_t qb = ((size_t)bp * 20 + h) * 1536;
        BULK_G2S(d,         g_Qhi + qb, 6144, bar);
        BULK_G2S(d + 6144,  g_Khi + qb, 6144, bar);
        size_t v0 = ((size_t)(bp * 2 + 0) * 20 + h) * 864;
        size_t v1 = ((size_t)(bp * 2 + 1) * 20 + h) * 864;
        BULK_G2S(d + 12288, g_Vhi + v0, 3456, bar);
        BULK_G2S(d + 15744, g_Vhi + v1, 3456, bar);
    };
    if (tid == 0) { stage(0); stage(1); stage(2); }

    const int tok0 = strip + g;
    const size_t pb25 = (size_t)bp * 25;

    for (int h = 0; h < NH; h++) {
        MBARRIER_WAIT_PARITY(fullB + (h % 3) * 8, (h / 3) & 1);

        const uint32_t* B  = sg + (h % 3) * AT_BUF;
        const uint32_t* Qh = B;
        const uint32_t* Kh = B + 1536;
        const uint32_t* Vh = B + 3072 + (wid >> 2) * 864;

        const int ra = tok0 * 12, rb2 = (tok0 + 8) * 12;
        uint32_t qh0[4] = { Qh[ra + q], Qh[rb2 + q], Qh[ra + q + 4], Qh[rb2 + q + 4] };
        uint32_t qh1[4] = { Qh[ra + 8 + q], Qh[rb2 + 8 + q], 0, 0 };

        float e[32];
        #pragma unroll
        for (int i = 0; i < 32; i++) e[i] = 0.f;
        #pragma unroll
        for (int nt = 0; nt < 8; nt++) {
            const int n = (rowoff + 8 * nt + g) * 12;
            mma16816h(e + nt * 4, qh0, Kh[n + q], Kh[n + q + 4]);
            mma16816h(e + nt * 4, qh1, Kh[n + 8 + q], 0u);
        }

        float rs0 = 0.f, rs8 = 0.f;
        #pragma unroll
        for (int nt = 0; nt < 8; nt++) {
            float e0 = __expf(e[nt*4+0] * 0.22360679774997896f);
            float e1 = __expf(e[nt*4+1] * 0.22360679774997896f);
            float e2 = __expf(e[nt*4+2] * 0.22360679774997896f);
            float e3 = __expf(e[nt*4+3] * 0.22360679774997896f);
            e[nt*4+0] = e0; e[nt*4+1] = e1; e[nt*4+2] = e2; e[nt*4+3] = e3;
            rs0 += e0 + e1; rs8 += e2 + e3;
        }
        rs0 += __shfl_xor_sync(0xffffffffu, rs0, 1);
        rs0 += __shfl_xor_sync(0xffffffffu, rs0, 2);
        rs8 += __shfl_xor_sync(0xffffffffu, rs8, 1);
        rs8 += __shfl_xor_sync(0xffffffffu, rs8, 2);

        uint32_t ph[4][4];
        #pragma unroll
        for (int t = 0; t < 4; t++) {
            ph[t][0] = pack_f16(e[8*t+0], e[8*t+1]);
            ph[t][1] = pack_f16(e[8*t+2], e[8*t+3]);
            ph[t][2] = pack_f16(e[8*t+4], e[8*t+5]);
            ph[t][3] = pack_f16(e[8*t+6], e[8*t+7]);
        }

        float cxa[12], cxb[12];
        #pragma unroll
        for (int i = 0; i < 12; i++) { cxa[i] = 0.f; cxb[i] = 0.f; }
        #pragma unroll
        for (int t = 0; t < 4; t += 2) {
            #pragma unroll
            for (int nj = 0; nj < 3; nj++) {
                const int na = (8 * nj + g) * 36 + 8 * t;
                const int nb = na + 8;
                mma16816h(cxa + nj * 4, ph[t],     Vh[na + q], Vh[na + q + 4]);
                mma16816h(cxb + nj * 4, ph[t + 1], Vh[nb + q], Vh[nb + q + 4]);
            }
        }

        if (lane == 0) MBARRIER_ARRIVE(emptyB + (h % 3) * 8);
        if (h + 3 < NH && tid == 0) stage(h + 3);

        const float i0 = 1.f / (rs0 + 1e-8f);
        const float i8 = 1.f / (rs8 + 1e-8f);
        #pragma unroll
        for (int nj = 0; nj < 3; nj++) {
            const int j0 = 8 * nj + 2 * q;
            if (j0 < 20) {
                float a0 = (cxa[nj*4+0] + cxb[nj*4+0]) * i0;
                float a1 = (cxa[nj*4+1] + cxb[nj*4+1]) * i0;
                float a2 = (cxa[nj*4+2] + cxb[nj*4+2]) * i8;
                float a3 = (cxa[nj*4+3] + cxb[nj*4+3]) * i8;
                const int p = 10 * h + 4 * nj + q;
                const int pl7 = (p & 7) ^ (4 * ((tok0 >> 2) & 1));
                const size_t base = (pb25 + (p >> 3)) * 128;
                g_ctxPhi[(base + tok0) * 8 + pl7]     = pack_f16(a0, a1);
                g_ctxPhi[(base + tok0 + 8) * 8 + pl7] = pack_f16(a2, a3);
            }
        }
    }

    __threadfence();
    __syncthreads();

    // ================= Phase 3: pooling (own 2 batch rows) =================
    float* b1s = (float*)(sg + P3_B1);
    float* w2s = (float*)(sg + P3_W2);
    float* lp  = (float*)(sg + P3_LP);
    if (tid < 200) { b1s[tid] = b1[tid]; w2s[tid] = W2[tid]; }
    __syncthreads();

    const int c8 = lane >> 2;
    const int pkey = c8 & 4;
    const int q0 = q ^ pkey, q1 = q0 ^ 4;
    const int pr0 = wid * 16 + c8;

    auto pstage = [&](int ks) {
        MBARRIER_WAIT_PARITY(pEmpty + (ks % 3) * 8, 1 ^ ((ks / 3) & 1));
        uint32_t bar = pFull + (ks % 3) * 8;
        int pass = ks / 25, k = ks % 25;
        uint32_t wbytes = pass ? 3072u : 3328u;
        MBARRIER_EXPECT_TX(bar, 4096 + wbytes);
        uint32_t d = sbase + (ks % 3) * P3_SLOT * 4;
        BULK_G2S(d,        g_ctxPhi + (pb25 + k) * 1024, 4096, bar);
        BULK_G2S(d + 4096, g_W1h + k * 1600 + pass * 832, wbytes, bar);
    };
    if (tid == 0) { pstage(0); pstage(1); pstage(2); }

    for (int pass = 0; pass < 2; pass++) {
        const int ntile = pass ? 12 : 13;
        const int tbase = pass * 13;
        float acc[52];
        #pragma unroll
        for (int i = 0; i < 52; i++) acc[i] = 0.f;

        for (int k = 0; k < 25; k++) {
            const int ks = pass * 25 + k;
            MBARRIER_WAIT_PARITY(pFull + (ks % 3) * 8, (ks / 3) & 1);

            const uint32_t* A  = sg + (ks % 3) * P3_SLOT;
            const uint32_t* Bh = A + 1024;

            uint32_t fh[4];
            fh[0] = A[pr0 * 8 + q0]; fh[1] = A[(pr0 + 8) * 8 + q0];
            fh[2] = A[pr0 * 8 + q1]; fh[3] = A[(pr0 + 8) * 8 + q1];

            #pragma unroll
            for (int t = 0; t < 13; t++) {
                if (t < ntile) {
                    const int cb = (t * 8 + c8) * 8;
                    mma16816h(acc + t * 4, fh, Bh[cb + q0], Bh[cb + q1]);
                }
            }
            if (lane == 0) MBARRIER_ARRIVE(pEmpty + (ks % 3) * 8);
            if (ks + 3 < 50 && tid == 0) pstage(ks + 3);
        }

        float part0 = 0.f, part8 = 0.f;
        #pragma unroll
        for (int t = 0; t < 13; t++) {
            if (t < ntile) {
                int c0 = (tbase + t) * 8 + 2 * q;
                part0 += tanh_fast(acc[t * 4 + 0] + b1s[c0])     * w2s[c0];
                part0 += tanh_fast(acc[t * 4 + 1] + b1s[c0 + 1]) * w2s[c0 + 1];
                part8 += tanh_fast(acc[t * 4 + 2] + b1s[c0])     * w2s[c0];
                part8 += tanh_fast(acc[t * 4 + 3] + b1s[c0 + 1]) * w2s[c0 + 1];
            }
        }
        part0 += __shfl_xor_sync(0xffffffffu, part0, 1);
        part0 += __shfl_xor_sync(0xffffffffu, part0, 2);
        part8 += __shfl_xor_sync(0xffffffffu, part8, 1);
        part8 += __shfl_xor_sync(0xffffffffu, part8, 2);
        if (q == 0) {
            if (pass == 0) { lp[pr0] = part0; lp[pr0 + 8] = part8; }
            else           { lp[pr0] += part0; lp[pr0 + 8] += part8; }
        }
    }
    __syncthreads();

    float* logit = (float*)(sg + P3_LOG);
    float* ssum  = (float*)(sg + P3_SUM);
    const float b2v = b2[0];
    if (tid < 128) logit[tid] = __expf(lp[tid] + b2v);
    __syncthreads();
    if (wid < 2) {
        float v = logit[wid * 64 + lane] + logit[wid * 64 + lane + 32];
        #pragma unroll
        for (int off = 16; off; off >>= 1) v += __shfl_xor_sync(0xffffffffu, v, off);
        if (lane == 0) ssum[wid] = v;
    }
    __syncthreads();

    if (tid < 200) {
        const int p = tid;
        const size_t fbase = (pb25 + (p >> 3)) * 128;
        const int ple = p & 7;
        #pragma unroll
        for (int bh = 0; bh < 2; bh++) {
            const float inv = 1.f / (ssum[bh] + 1e-8f);
            const float* lg = logit + bh * 64;
            float ax = 0.f, ay = 0.f;
            #pragma unroll 4
            for (int l = 0; l < 64; l++) {
                const int t = bh * 64 + l;
                uint32_t w32 = g_ctxPhi[(fbase + t) * 8 + (ple ^ (4 * ((t >> 2) & 1)))];
                __half2 hv = *(__half2*)&w32;
                float w = lg[l];
                ax += w * __low2float(hv);
                ay += w * __high2float(hv);
            }
            ((float2*)out)[(size_t)(bp * 2 + bh) * 200 + p] = make_float2(ax * inv, ay * inv);
        }
    }
}

// ---------------------------------------------------------------------------
extern "C" void kernel_launch(void* const* d_in, const int* in_sizes, int n_in,
                              void* d_out, int out_size) {
    const int*   text = (const int*)  d_in[0];
    const float* emb  = (const float*)d_in[1];
    const float* WQ   = (const float*)d_in[2];
    const float* bQ   = (const float*)d_in[3];
    const float* WK   = (const float*)d_in[4];
    const float* bK   = (const float*)d_in[5];
    const float* WV   = (const float*)d_in[6];
    const float* bV   = (const float*)d_in[7];
    const float* W1   = (const float*)d_in[8];
    const float* b1   = (const float*)d_in[9];
    const float* W2   = (const float*)d_in[10];
    const float* b2   = (const float*)d_in[11];
    float* out = (float*)d_out;

    convert_w<<<(1200 * 160 + 200 * 200 + 255) / 256, 256>>>(WQ, WK, WV, W1);

    cudaFuncSetAttribute(gemm_attn, cudaFuncAttributeMaxDynamicSharedMemorySize, SMEM_GA);
    gemm_attn<<<NB / 2, 256, SMEM_GA>>>(text, emb, bQ, bK, bV, b1, W2, b2, out);
}

// round 17
// speedup vs baseline: 1.5044x; 1.1047x over previous
#include <cuda_runtime.h>
#include <cuda_bf16.h>
#include <cuda_fp16.h>
#include <cstdint>
#include <math.h>

#define NB 2048
#define SL 64
#define NH 20
#define DEMB 300
#define HDIM 400
#define F1 200

// ---------------------------------------------------------------------------
// Global scratch (all operand tensors single fp16)
// ---------------------------------------------------------------------------
__device__ uint32_t g_Bh[1200 * 160];      // QKV weights, fp16 kpairs, LDS64-paired layout
__device__ uint32_t g_W1h[25 * 200 * 8];   // W1 fp16 fragments (paired rows)
__device__ uint32_t g_Qhi[(size_t)1024 * 20 * 128 * 12];  // Q fp16 [pair][head][tok][12]
__device__ uint32_t g_Khi[(size_t)1024 * 20 * 128 * 12];  // K fp16
__device__ uint32_t g_Vhi[(size_t)2048 * 20 * 24 * 36];   // V fp16 [row][head][j][36]
__device__ uint32_t g_ctxPhi[(size_t)1024 * 25 * 128 * 8]; // ctx fp16 fragments (paired rows)

__device__ __forceinline__ uint32_t pack_f16(float a, float b) {
    __half2 t = __floats2half2_rn(a, b);
    return *(uint32_t*)&t;
}
__device__ __forceinline__ uint32_t smem_u32(const void* p) {
    uint32_t a;
    asm("{ .reg .u64 t; cvta.to.shared.u64 t, %1; cvt.u32.u64 %0, t; }" : "=r"(a) : "l"(p));
    return a;
}
__device__ __forceinline__ float tanh_fast(float x) {
    float y;
    asm("tanh.approx.f32 %0, %1;" : "=f"(y) : "f"(x));
    return y;
}
__device__ __forceinline__ void mma16816h(float* d, const uint32_t* a, uint32_t b0, uint32_t b1) {
    asm volatile(
        "mma.sync.aligned.m16n8k16.row.col.f32.f16.f16.f32 "
        "{%0,%1,%2,%3}, {%4,%5,%6,%7}, {%8,%9}, {%0,%1,%2,%3};"
        : "+f"(d[0]), "+f"(d[1]), "+f"(d[2]), "+f"(d[3])
        : "r"(a[0]), "r"(a[1]), "r"(a[2]), "r"(a[3]), "r"(b0), "r"(b1));
}

#define MBARRIER_INIT(mbar, cnt) \
    asm volatile("mbarrier.init.shared.b64 [%0], %1;" :: "r"((uint32_t)(mbar)), "r"((uint32_t)(cnt)) : "memory")
#define MBARRIER_EXPECT_TX(mbar, tx) \
    asm volatile("mbarrier.arrive.expect_tx.shared.b64 _, [%0], %1;" :: "r"((uint32_t)(mbar)), "r"((uint32_t)(tx)) : "memory")
#define MBARRIER_ARRIVE(mbar) \
    asm volatile("mbarrier.arrive.shared.b64 _, [%0];" :: "r"((uint32_t)(mbar)) : "memory")
#define MBARRIER_WAIT_PARITY(mbar, par) do {                                     \
    uint32_t _m = (uint32_t)(mbar); uint32_t _p = (uint32_t)(par); uint32_t _d;  \
    asm volatile("{\n\t.reg .pred p;\n\t"                                        \
        "mbarrier.try_wait.parity.acquire.cta.shared::cta.b64 p, [%1], %2;\n\t"  \
        "selp.b32 %0, 1, 0, p;\n\t}" : "=r"(_d) : "r"(_m), "r"(_p) : "memory");  \
    if (!_d) {                                                                   \
        asm volatile("{\n\t.reg .pred P1;\n\t"                                   \
        "WAIT_LOOP_%=:\n\t"                                                      \
        "mbarrier.try_wait.parity.acquire.cta.shared::cta.b64 P1, [%0], %1, 0x989680;\n\t" \
        "@P1 bra.uni WAIT_DONE_%=;\n\t"                                          \
        "bra.uni WAIT_LOOP_%=;\n\t"                                              \
        "WAIT_DONE_%=:\n\t}" :: "r"(_m), "r"(_p) : "memory");                    \
    }                                                                            \
} while (0)
#define BULK_G2S(dst, src, bytes, bar)                                           \
    asm volatile("cp.async.bulk.shared::cluster.global.mbarrier::complete_tx::bytes [%0], [%1], %2, [%3];" \
        :: "r"((uint32_t)(dst)), "l"(src), "r"((uint32_t)(bytes)), "r"((uint32_t)(bar)) : "memory")

// ---------------------------------------------------------------------------
// Kernel 1: weight conversion
// ---------------------------------------------------------------------------
__global__ void convert_w(const float* __restrict__ WQ,
                          const float* __restrict__ WK,
                          const float* __restrict__ WV,
                          const float* __restrict__ W1)
{
    int idx = blockIdx.x * 256 + threadIdx.x;
    if (idx < 1200 * 160) {
        int n = idx / 160, p = idx % 160;
        int mat = n / 400, col = n - mat * 400;
        const float* W = (mat == 0) ? WQ : (mat == 1) ? WK : WV;
        int k = 2 * p;
        float w0 = (k < DEMB) ? W[k * 400 + col] : 0.f;
        float w1 = (k + 1 < DEMB) ? W[(k + 1) * 400 + col] : 0.f;
        int newp = (p & ~7) | (2 * (p & 3)) | ((p >> 2) & 1);
        int gg = n & 7;
        int sw = ((gg & 3) << 3) | (((gg >> 2) & 1) << 1);
        g_Bh[n * 160 + (newp ^ sw)] = pack_f16(w0, w1);
    } else if (idx < 1200 * 160 + 200 * 200) {
        int j = idx - 1200 * 160;
        int col = j % 200, p = j / 200;
        float w0 = W1[(2 * p) * 200 + col];
        float w1 = W1[(2 * p + 1) * 200 + col];
        int u = p & 7;
        int nu = 2 * (u & 3) + (u >> 2);          // LDS64 pairing, no swizzle
        g_W1h[(p >> 3) * 1600 + col * 8 + nu] = pack_f16(w0, w1);
    }
}

// ---------------------------------------------------------------------------
// Kernel 2: FUSED QKV GEMM + attention + pooling
// ---------------------------------------------------------------------------
#define XW 164
#define GW_BUF0 0
#define GW_BUF1 6400
#define GW_SOUT0 12800
#define GW_SOUT1 18080
#define GW_XHI  0
#define GW_BIAS 23360
#define GW_MBAR 24560
#define AT_BUF  4800
#define AT_FULL 24564
#define AT_EMPT 24570
#define P3_SLOT 1856
#define P3_B1   5568
#define P3_W2   5768
#define P3_LP   5968
#define P3_LOG  6096
#define P3_SUM  6224
#define P3_FULL 24576
#define P3_EMPT 24582
#define SMEM_GA (24592 * 4)

__global__ __launch_bounds__(256, 2)
void gemm_attn(const int*   __restrict__ text,
               const float* __restrict__ emb,
               const float* __restrict__ bQ,
               const float* __restrict__ bK,
               const float* __restrict__ bV,
               const float* __restrict__ b1,
               const float* __restrict__ W2,
               const float* __restrict__ b2,
               float* __restrict__ out)
{
    extern __shared__ uint32_t sg[];
    const uint32_t sbase = smem_u32(sg);
    const int tid = threadIdx.x;
    const int lane = tid & 31;
    const int wid = tid >> 5;
    const int q = lane & 3;
    const int g = lane >> 2;
    const int bp = blockIdx.x;
    const uint32_t bar0 = sbase + GW_MBAR * 4;
    const uint32_t bar1 = bar0 + 8;
    const uint32_t fullB  = sbase + AT_FULL * 4;
    const uint32_t emptyB = sbase + AT_EMPT * 4;
    const uint32_t pFull  = sbase + P3_FULL * 4;
    const uint32_t pEmpty = sbase + P3_EMPT * 4;

    if (tid == 0) {
        MBARRIER_INIT(bar0, 1); MBARRIER_INIT(bar1, 1);
        #pragma unroll
        for (int i = 0; i < 3; i++) {
            MBARRIER_INIT(fullB + i * 8, 1);
            MBARRIER_INIT(emptyB + i * 8, 8);
            MBARRIER_INIT(pFull + i * 8, 1);
            MBARRIER_INIT(pEmpty + i * 8, 8);
        }
    }

    float* bias_s = (float*)(sg + GW_BIAS);
    for (int i = tid; i < 400; i += 256) {
        bias_s[i] = bQ[i]; bias_s[400 + i] = bK[i]; bias_s[800 + i] = bV[i];
    }

    // ================= Phase 1: QKV GEMM =================
    uint32_t* xhi = sg + GW_XHI;
    for (int i = tid; i < 128 * 14; i += 256) {
        int r = i / 14, w = 150 + i % 14;
        xhi[r * XW + w] = 0;
    }
    {
        const float4* emb4 = (const float4*)emb;
        const int* trow = text + bp * 128;
        for (int i = tid; i < 128 * 75; i += 256) {
            int r = i / 75, c = i % 75;
            int tok = trow[r];
            float4 v = emb4[(size_t)tok * 75 + c];
            xhi[r * XW + 2 * c]     = pack_f16(v.x, v.y);
            xhi[r * XW + 2 * c + 1] = pack_f16(v.z, v.w);
        }
    }
    __syncthreads();

    uint32_t ahi[20][4];
    {
        const int r0 = wid * 16 + g;
        const int r1 = r0 + 8;
        #pragma unroll
        for (int kk = 0; kk < 20; kk++) {
            int w0 = 8 * kk + q;
            ahi[kk][0] = xhi[r0 * XW + w0];
            ahi[kk][1] = xhi[r1 * XW + w0];
            ahi[kk][2] = xhi[r0 * XW + w0 + 4];
            ahi[kk][3] = xhi[r1 * XW + w0 + 4];
        }
    }
    __syncthreads();   // x region dead

    auto prefetch = [&](int chunk, uint32_t dstw, uint32_t bar) {
        MBARRIER_EXPECT_TX(bar, 25600);
        BULK_G2S(sbase + dstw * 4, g_Bh + chunk * 6400, 25600, bar);
    };
    if (tid == 0) prefetch(0, GW_BUF0, bar0);

    const int sw = ((g & 3) << 3) | (((g >> 2) & 1) << 1);

    for (int c = 0; c < 30; c++) {
        if (c + 1 < 30 && tid == 0)
            prefetch(c + 1, (c & 1) ? GW_BUF0 : GW_BUF1, (c & 1) ? bar0 : bar1);
        MBARRIER_WAIT_PARITY((c & 1) ? bar1 : bar0, (c >> 1) & 1);

        const uint32_t* Bh = sg + ((c & 1) ? GW_BUF1 : GW_BUF0);
        float* sout = (float*)(sg + ((c & 1) ? GW_SOUT1 : GW_SOUT0));
        const int r0 = wid * 16 + g;
        const int mat = c / 10, hpair = c % 10;

        #pragma unroll
        for (int i = 0; i < 5; i++) {
            float acc0[4] = {0.f, 0.f, 0.f, 0.f};
            float acc1[4] = {0.f, 0.f, 0.f, 0.f};
            const int base = (i * 8 + g) * 160;
            #pragma unroll
            for (int kk = 0; kk < 20; kk += 2) {
                uint2 b0 = *(const uint2*)(Bh + base + ((8 * kk + 2 * q) ^ sw));
                uint2 b1 = *(const uint2*)(Bh + base + ((8 * (kk + 1) + 2 * q) ^ sw));
                mma16816h(acc0, ahi[kk],     b0.x, b0.y);
                mma16816h(acc1, ahi[kk + 1], b1.x, b1.y);
            }
            int cl = i * 8 + 2 * q;
            if (mat < 2) {
                // direct STG: thread owns word p of token rows r0, r0+8
                const int hl = (cl >= 20) ? 1 : 0;
                const int p = (cl - 20 * hl) >> 1;
                const float bb0 = bias_s[c * 40 + cl];
                const float bb1 = bias_s[c * 40 + cl + 1];
                uint32_t* dst = (mat ? g_Khi : g_Qhi)
                              + ((size_t)bp * 20 + hpair * 2 + hl) * 1536;
                dst[(size_t)r0 * 12 + p]       = pack_f16(acc0[0] + acc1[0] + bb0,
                                                          acc0[1] + acc1[1] + bb1);
                dst[(size_t)(r0 + 8) * 12 + p] = pack_f16(acc0[2] + acc1[2] + bb0,
                                                          acc0[3] + acc1[3] + bb1);
            } else {
                sout[cl * 132 + r0]           = acc0[0] + acc1[0];
                sout[(cl + 1) * 132 + r0]     = acc0[1] + acc1[1];
                sout[cl * 132 + r0 + 8]       = acc0[2] + acc1[2];
                sout[(cl + 1) * 132 + r0 + 8] = acc0[3] + acc1[3];
            }
        }
        __syncthreads();   // guards B-buffer recycle (and sout for V)

        if (mat == 2 && tid < 160) {
            const int hl = tid / 80, r = tid % 80, j = r >> 2, qt = r & 3;
            const int head = hpair * 2 + hl, row = qt >> 1;
            const float bb = bias_s[c * 40 + hl * 20 + j];
            uint32_t hv[16];
            #pragma unroll
            for (int i = 0; i < 16; i++) {
                int t = qt * 32 + 2 * i;
                float v0 = sout[(hl * 20 + j) * 132 + t]     + bb;
                float v1 = sout[(hl * 20 + j) * 132 + t + 1] + bb;
                hv[i] = pack_f16(v0, v1);
            }
            size_t vb = (((size_t)(bp * 2 + row) * 20 + head) * 24 + j) * 36 + 16 * (qt & 1);
            uint32_t* dh = g_Vhi + vb;
            #pragma unroll
            for (int u = 0; u < 4; u++)
                ((uint4*)dh)[u] = make_uint4(hv[4*u], hv[4*u+1], hv[4*u+2], hv[4*u+3]);
        }
    }

    __threadfence();
    __syncthreads();

    // ================= Phase 2: attention =================
    const int strip = wid * 16;
    const int rowoff = (wid >> 2) * 64;

    auto stage = [&](int h) {
        MBARRIER_WAIT_PARITY(emptyB + (h % 3) * 8, 1 ^ ((h / 3) & 1));
        uint32_t bar = fullB + (h % 3) * 8;
        uint32_t d = sbase + (h % 3) * AT_BUF * 4;
        MBARRIER_EXPECT_TX(bar, 19200);
        size_t qb = ((size_t)bp * 20 + h) * 1536;
        BULK_G2S(d,         g_Qhi + qb, 6144, bar);
        BULK_G2S(d + 6144,  g_Khi + qb, 6144, bar);
        size_t v0 = ((size_t)(bp * 2 + 0) * 20 + h) * 864;
        size_t v1 = ((size_t)(bp * 2 + 1) * 20 + h) * 864;
        BULK_G2S(d + 12288, g_Vhi + v0, 3456, bar);
        BULK_G2S(d + 15744, g_Vhi + v1, 3456, bar);
    };
    if (tid == 0) { stage(0); stage(1); stage(2); }

    const int tok0 = strip + g;
    const size_t pb25 = (size_t)bp * 25;

    for (int h = 0; h < NH; h++) {
        MBARRIER_WAIT_PARITY(fullB + (h % 3) * 8, (h / 3) & 1);

        const uint32_t* B  = sg + (h % 3) * AT_BUF;
        const uint32_t* Qh = B;
        const uint32_t* Kh = B + 1536;
        const uint32_t* Vh = B + 3072 + (wid >> 2) * 864;

        const int ra = tok0 * 12, rb2 = (tok0 + 8) * 12;
        uint32_t qh0[4] = { Qh[ra + q], Qh[rb2 + q], Qh[ra + q + 4], Qh[rb2 + q + 4] };
        uint32_t qh1[4] = { Qh[ra + 8 + q], Qh[rb2 + 8 + q], 0, 0 };

        float e[32];
        #pragma unroll
        for (int i = 0; i < 32; i++) e[i] = 0.f;
        #pragma unroll
        for (int nt = 0; nt < 8; nt++) {
            const int n = (rowoff + 8 * nt + g) * 12;
            mma16816h(e + nt * 4, qh0, Kh[n + q], Kh[n + q + 4]);
            mma16816h(e + nt * 4, qh1, Kh[n + 8 + q], 0u);
        }

        float rs0 = 0.f, rs8 = 0.f;
        #pragma unroll
        for (int nt = 0; nt < 8; nt++) {
            float e0 = __expf(e[nt*4+0] * 0.22360679774997896f);
            float e1 = __expf(e[nt*4+1] * 0.22360679774997896f);
            float e2 = __expf(e[nt*4+2] * 0.22360679774997896f);
            float e3 = __expf(e[nt*4+3] * 0.22360679774997896f);
            e[nt*4+0] = e0; e[nt*4+1] = e1; e[nt*4+2] = e2; e[nt*4+3] = e3;
            rs0 += e0 + e1; rs8 += e2 + e3;
        }
        rs0 += __shfl_xor_sync(0xffffffffu, rs0, 1);
        rs0 += __shfl_xor_sync(0xffffffffu, rs0, 2);
        rs8 += __shfl_xor_sync(0xffffffffu, rs8, 1);
        rs8 += __shfl_xor_sync(0xffffffffu, rs8, 2);

        uint32_t ph[4][4];
        #pragma unroll
        for (int t = 0; t < 4; t++) {
            ph[t][0] = pack_f16(e[8*t+0], e[8*t+1]);
            ph[t][1] = pack_f16(e[8*t+2], e[8*t+3]);
            ph[t][2] = pack_f16(e[8*t+4], e[8*t+5]);
            ph[t][3] = pack_f16(e[8*t+6], e[8*t+7]);
        }

        float cxa[12], cxb[12];
        #pragma unroll
        for (int i = 0; i < 12; i++) { cxa[i] = 0.f; cxb[i] = 0.f; }
        #pragma unroll
        for (int t = 0; t < 4; t += 2) {
            #pragma unroll
            for (int nj = 0; nj < 3; nj++) {
                const int na = (8 * nj + g) * 36 + 8 * t;
                const int nb = na + 8;
                mma16816h(cxa + nj * 4, ph[t],     Vh[na + q], Vh[na + q + 4]);
                mma16816h(cxb + nj * 4, ph[t + 1], Vh[nb + q], Vh[nb + q + 4]);
            }
        }

        if (lane == 0) MBARRIER_ARRIVE(emptyB + (h % 3) * 8);
        if (h + 3 < NH && tid == 0) stage(h + 3);

        const float i0 = 1.f / (rs0 + 1e-8f);
        const float i8 = 1.f / (rs8 + 1e-8f);
        #pragma unroll
        for (int nj = 0; nj < 3; nj++) {
            const int j0 = 8 * nj + 2 * q;
            if (j0 < 20) {
                float a0 = (cxa[nj*4+0] + cxb[nj*4+0]) * i0;
                float a1 = (cxa[nj*4+1] + cxb[nj*4+1]) * i0;
                float a2 = (cxa[nj*4+2] + cxb[nj*4+2]) * i8;
                float a3 = (cxa[nj*4+3] + cxb[nj*4+3]) * i8;
                const int p = 10 * h + 4 * nj + q;
                const int u = p & 7;
                const int nu = 2 * (u & 3) + (u >> 2);   // paired layout
                const size_t base = (pb25 + (p >> 3)) * 128;
                g_ctxPhi[(base + tok0) * 8 + nu]     = pack_f16(a0, a1);
                g_ctxPhi[(base + tok0 + 8) * 8 + nu] = pack_f16(a2, a3);
            }
        }
    }

    __threadfence();
    __syncthreads();

    // ================= Phase 3: pooling =================
    float* b1s = (float*)(sg + P3_B1);
    float* w2s = (float*)(sg + P3_W2);
    float* lp  = (float*)(sg + P3_LP);
    if (tid < 200) { b1s[tid] = b1[tid]; w2s[tid] = W2[tid]; }
    __syncthreads();

    const int c8 = lane >> 2;
    const int pr0 = wid * 16 + c8;

    auto pstage = [&](int ks) {
        MBARRIER_WAIT_PARITY(pEmpty + (ks % 3) * 8, 1 ^ ((ks / 3) & 1));
        uint32_t bar = pFull + (ks % 3) * 8;
        int pass = ks / 25, k = ks % 25;
        uint32_t wbytes = pass ? 3072u : 3328u;
        MBARRIER_EXPECT_TX(bar, 4096 + wbytes);
        uint32_t d = sbase + (ks % 3) * P3_SLOT * 4;
        BULK_G2S(d,        g_ctxPhi + (pb25 + k) * 1024, 4096, bar);
        BULK_G2S(d + 4096, g_W1h + k * 1600 + pass * 832, wbytes, bar);
    };
    if (tid == 0) { pstage(0); pstage(1); pstage(2); }

    for (int pass = 0; pass < 2; pass++) {
        const int ntile = pass ? 12 : 13;
        const int tbase = pass * 13;
        float acc[52];
        #pragma unroll
        for (int i = 0; i < 52; i++) acc[i] = 0.f;

        for (int k = 0; k < 25; k++) {
            const int ks = pass * 25 + k;
            MBARRIER_WAIT_PARITY(pFull + (ks % 3) * 8, (ks / 3) & 1);

            const uint32_t* A  = sg + (ks % 3) * P3_SLOT;
            const uint32_t* Bh = A + 1024;

            uint2 u0 = *(const uint2*)(A + pr0 * 8 + 2 * q);
            uint2 u1 = *(const uint2*)(A + (pr0 + 8) * 8 + 2 * q);
            uint32_t fh[4] = { u0.x, u1.x, u0.y, u1.y };

            #pragma unroll
            for (int t = 0; t < 13; t++) {
                if (t < ntile) {
                    const int cb = (t * 8 + c8) * 8;
                    uint2 b = *(const uint2*)(Bh + cb + 2 * q);
                    mma16816h(acc + t * 4, fh, b.x, b.y);
                }
            }
            if (lane == 0) MBARRIER_ARRIVE(pEmpty + (ks % 3) * 8);
            if (ks + 3 < 50 && tid == 0) pstage(ks + 3);
        }

        float part0 = 0.f, part8 = 0.f;
        #pragma unroll
        for (int t = 0; t < 13; t++) {
            if (t < ntile) {
                int c0 = (tbase + t) * 8 + 2 * q;
                part0 += tanh_fast(acc[t * 4 + 0] + b1s[c0])     * w2s[c0];
                part0 += tanh_fast(acc[t * 4 + 1] + b1s[c0 + 1]) * w2s[c0 + 1];
                part8 += tanh_fast(acc[t * 4 + 2] + b1s[c0])     * w2s[c0];
                part8 += tanh_fast(acc[t * 4 + 3] + b1s[c0 + 1]) * w2s[c0 + 1];
            }
        }
        part0 += __shfl_xor_sync(0xffffffffu, part0, 1);
        part0 += __shfl_xor_sync(0xffffffffu, part0, 2);
        part8 += __shfl_xor_sync(0xffffffffu, part8, 1);
        part8 += __shfl_xor_sync(0xffffffffu, part8, 2);
        if (q == 0) {
            if (pass == 0) { lp[pr0] = part0; lp[pr0 + 8] = part8; }
            else           { lp[pr0] += part0; lp[pr0 + 8] += part8; }
        }
    }
    __syncthreads();

    float* logit = (float*)(sg + P3_LOG);
    float* ssum  = (float*)(sg + P3_SUM);
    const float b2v = b2[0];
    if (tid < 128) logit[tid] = __expf(lp[tid] + b2v);
    __syncthreads();
    if (wid < 2) {
        float v = logit[wid * 64 + lane] + logit[wid * 64 + lane + 32];
        #pragma unroll
        for (int off = 16; off; off >>= 1) v += __shfl_xor_sync(0xffffffffu, v, off);
        if (lane == 0) ssum[wid] = v;
    }
    __syncthreads();

    if (tid < 200) {
        const int p = tid;
        const size_t fbase = (pb25 + (p >> 3)) * 128;
        const int u7 = p & 7;
        const int nu = 2 * (u7 & 3) + (u7 >> 2);
        #pragma unroll
        for (int bh = 0; bh < 2; bh++) {
            const float inv = 1.f / (ssum[bh] + 1e-8f);
            const float* lg = logit + bh * 64;
            float ax = 0.f, ay = 0.f;
            #pragma unroll 4
            for (int l = 0; l < 64; l++) {
                const int t = bh * 64 + l;
                uint32_t w32 = g_ctxPhi[(fbase + t) * 8 + nu];
                __half2 hv = *(__half2*)&w32;
                float w = lg[l];
                ax += w * __low2float(hv);
                ay += w * __high2float(hv);
            }
            ((float2*)out)[(size_t)(bp * 2 + bh) * 200 + p] = make_float2(ax * inv, ay * inv);
        }
    }
}

// ---------------------------------------------------------------------------
extern "C" void kernel_launch(void* const* d_in, const int* in_sizes, int n_in,
                              void* d_out, int out_size) {
    const int*   text = (const int*)  d_in[0];
    const float* emb  = (const float*)d_in[1];
    const float* WQ   = (const float*)d_in[2];
    const float* bQ   = (const float*)d_in[3];
    const float* WK   = (const float*)d_in[4];
    const float* bK   = (const float*)d_in[5];
    const float* WV   = (const float*)d_in[6];
    const float* bV   = (const float*)d_in[7];
    const float* W1   = (const float*)d_in[8];
    const float* b1   = (const float*)d_in[9];
    const float* W2   = (const float*)d_in[10];
    const float* b2   = (const float*)d_in[11];
    float* out = (float*)d_out;

    convert_w<<<(1200 * 160 + 200 * 200 + 255) / 256, 256>>>(WQ, WK, WV, W1);

    cudaFuncSetAttribute(gemm_attn, cudaFuncAttributeMaxDynamicSharedMemorySize, SMEM_GA);
    gemm_attn<<<NB / 2, 256, SMEM_GA>>>(text, emb, bQ, bK, bV, b1, W2, b2, out);
}